// round 7
// baseline (speedup 1.0000x reference)
#include <cuda_runtime.h>
#include <math.h>

#define N_IN   512
#define N_OUT  10
#define D_OUT  16
#define D_IN   8
#define NJD    (N_OUT * D_OUT)    // 160 outputs
#define NBLK   (NJD / 2)          // 80 blocks, 2 jd each
#define NWARP  16
#define NTHR   (NWARP * 32)       // 512 threads
#define EPS    1e-7f

// Block b handles jd0 = 2b and jd0+1 (adjacent in memory -> 64B-contiguous
// W reads per n-row). Lane layout: half = lane&1 (k-half), jd_sel = (lane>>1)&1,
// n_off = lane>>2 (0..7). Warp w covers n in [w*32, w*32+32) striding 8:
// 4 iterations x (1 W float4 + 1 x float4) = 8 independent LDG.128 per lane.
// Each W-LDG touches only 8 distinct 128B lines per warp (64B contiguous per
// n-row spanning both jds) vs 16 in the 1-jd layout.
__global__ __launch_bounds__(NTHR) void digitcaps_jd2(
    const float* __restrict__ x,   // (512, 8)
    const float* __restrict__ W,   // (512, 160, 8) contiguous
    float* __restrict__ out)       // 160 floats
{
    __shared__ float s_part[NWARP * 2];

    const int jd0    = blockIdx.x * 2;
    const int warp   = threadIdx.x >> 5;     // 0..15
    const int lane   = threadIdx.x & 31;
    const int half   = lane & 1;              // 0..1 (k-half)
    const int jd_sel = (lane >> 1) & 1;       // 0..1
    const int n_off  = lane >> 2;             // 0..7

    const int jd = jd0 + jd_sel;
    const int n0 = warp * 32 + n_off;

    float4 w4[4], x4[4];
#pragma unroll
    for (int i = 0; i < 4; ++i) {
        const int n = n0 + i * 8;
        w4[i] = *reinterpret_cast<const float4*>(
            W + ((size_t)n * NJD + jd) * D_IN + half * 4);
        x4[i] = *reinterpret_cast<const float4*>(
            x + (size_t)n * D_IN + half * 4);
    }

    float acc0 = 0.0f, acc1 = 0.0f;
#pragma unroll
    for (int i = 0; i < 4; i += 2) {
        acc0 = fmaf(w4[i].x,   x4[i].x,   acc0);
        acc0 = fmaf(w4[i].y,   x4[i].y,   acc0);
        acc0 = fmaf(w4[i].z,   x4[i].z,   acc0);
        acc0 = fmaf(w4[i].w,   x4[i].w,   acc0);
        acc1 = fmaf(w4[i+1].x, x4[i+1].x, acc1);
        acc1 = fmaf(w4[i+1].y, x4[i+1].y, acc1);
        acc1 = fmaf(w4[i+1].z, x4[i+1].z, acc1);
        acc1 = fmaf(w4[i+1].w, x4[i+1].w, acc1);
    }
    float acc = acc0 + acc1;

    // Reduce over half (xor 1) and n_off (xor 4,8,16); jd_sel (bit 1) preserved.
    acc += __shfl_xor_sync(0xFFFFFFFFu, acc, 1);
    acc += __shfl_xor_sync(0xFFFFFFFFu, acc, 4);
    acc += __shfl_xor_sync(0xFFFFFFFFu, acc, 8);
    acc += __shfl_xor_sync(0xFFFFFFFFu, acc, 16);

    if (lane < 4 && half == 0)                 // lanes 0 (jd_sel=0) and 2 (jd_sel=1)
        s_part[warp * 2 + jd_sel] = acc;
    __syncthreads();

    // Warp 0: 32 partials laid out [w*2 + jd_sel]. Reduce over w bits
    // (xor 2,4,8,16), preserving jd_sel (bit 0). Lanes 0 and 1 hold totals.
    if (warp == 0) {
        float s = s_part[lane];
        s += __shfl_xor_sync(0xFFFFFFFFu, s, 2);
        s += __shfl_xor_sync(0xFFFFFFFFu, s, 4);
        s += __shfl_xor_sync(0xFFFFFFFFu, s, 8);
        s += __shfl_xor_sync(0xFFFFFFFFu, s, 16);

        if (lane < 2) {
            s *= (1.0f / (float)N_IN);
            const float sq   = s * s;
            const float norm = s / (sqrtf(sq + EPS) + EPS);
            out[jd0 + lane] = (sq / (1.0f + sq)) * norm;
        }
    }
}

extern "C" void kernel_launch(void* const* d_in, const int* in_sizes, int n_in,
                              void* d_out, int out_size)
{
    const float* x;
    const float* W;
    if (in_sizes[0] == N_IN * D_IN) {
        x = (const float*)d_in[0];
        W = (const float*)d_in[1];
    } else {
        x = (const float*)d_in[1];
        W = (const float*)d_in[0];
    }
    float* out = (float*)d_out;

    digitcaps_jd2<<<NBLK, NTHR>>>(x, W, out);
}